// round 5
// baseline (speedup 1.0000x reference)
#include <cuda_runtime.h>

// Problem constants (fixed by setup_inputs)
#define BB 2
#define TT 2048
#define DD 1024
#define HH 16
#define HD 64

// Scratch: q,k,v,y in [B,H,T,hd] layout
__device__ float g_q[BB*HH*TT*HD];
__device__ float g_k[BB*HH*TT*HD];
__device__ float g_v[BB*HH*TT*HD];
__device__ float g_y[BB*HH*TT*HD];

// ---------------------------------------------------------------------------
// Kernel 1: qk = x_norm @ qk_w^T + qk_b, scattered directly into g_q / g_k
// M=4096 (b*T+t), N=2048 (2*D cols), K=1024
// 128x128 block tile, BK=16, 256 threads, 8x8 per-thread micro-tile.
// Smem stride 132 words (528B): 16B-aligned rows -> float4 fragment loads,
// conflict-free in the hot loop.
// ---------------------------------------------------------------------------
#define GSTRIDE 132

__global__ __launch_bounds__(256) void qk_gemm_kernel(
    const float* __restrict__ X,      // [4096,1024]
    const float* __restrict__ W,      // [2048,1024]
    const float* __restrict__ bias)   // [2048]
{
    const int K = 1024;
    __shared__ float As[16][GSTRIDE];   // [k][m]
    __shared__ float Bs[16][GSTRIDE];   // [k][n]

    const int tid = threadIdx.x;
    const int tx = tid & 15;
    const int ty = tid >> 4;
    const int m0 = blockIdx.y * 128;
    const int n0 = blockIdx.x * 128;

    float acc[8][8];
    #pragma unroll
    for (int i = 0; i < 8; i++)
        #pragma unroll
        for (int j = 0; j < 8; j++) acc[i][j] = 0.f;

    for (int kt = 0; kt < K; kt += 16) {
        #pragma unroll
        for (int it = 0; it < 2; it++) {
            int idx = tid + it * 256;          // 0..511
            int row = idx >> 2;                // 0..127
            int kq  = (idx & 3) << 2;          // 0,4,8,12
            float4 va = *(const float4*)&X[(size_t)(m0 + row) * K + kt + kq];
            As[kq+0][row] = va.x; As[kq+1][row] = va.y;
            As[kq+2][row] = va.z; As[kq+3][row] = va.w;
            float4 vb = *(const float4*)&W[(size_t)(n0 + row) * K + kt + kq];
            Bs[kq+0][row] = vb.x; Bs[kq+1][row] = vb.y;
            Bs[kq+2][row] = vb.z; Bs[kq+3][row] = vb.w;
        }
        __syncthreads();
        #pragma unroll
        for (int k = 0; k < 16; k++) {
            float a[8], b[8];
            // float4 fragment loads: conflict-free / broadcast
            float4 a0 = *(const float4*)&As[k][ty * 8];
            float4 a1 = *(const float4*)&As[k][ty * 8 + 4];
            float4 b0 = *(const float4*)&Bs[k][tx * 8];
            float4 b1 = *(const float4*)&Bs[k][tx * 8 + 4];
            a[0]=a0.x; a[1]=a0.y; a[2]=a0.z; a[3]=a0.w;
            a[4]=a1.x; a[5]=a1.y; a[6]=a1.z; a[7]=a1.w;
            b[0]=b0.x; b[1]=b0.y; b[2]=b0.z; b[3]=b0.w;
            b[4]=b1.x; b[5]=b1.y; b[6]=b1.z; b[7]=b1.w;
            #pragma unroll
            for (int i = 0; i < 8; i++)
                #pragma unroll
                for (int j = 0; j < 8; j++)
                    acc[i][j] = fmaf(a[i], b[j], acc[i][j]);
        }
        __syncthreads();
    }

    // Epilogue: add bias, scatter into head-major q/k
    #pragma unroll
    for (int i = 0; i < 8; i++) {
        int m = m0 + ty * 8 + i;
        int b = m >> 11;          // /2048
        int t = m & 2047;
        #pragma unroll
        for (int j = 0; j < 8; j++) {
            int n = n0 + tx * 8 + j;
            float v = acc[i][j] + bias[n];
            int nn = n & 1023;
            int h = nn >> 6;
            int d = nn & 63;
            size_t off = ((size_t)((b * HH + h) * TT + t)) * HD + d;
            if (n < 1024) g_q[off] = v;
            else          g_k[off] = v;
        }
    }
}

// ---------------------------------------------------------------------------
// Kernel 2: v[b,i,t,d] = sum_j v_fact[i,j] * xt[b,t,j*64+d]
// ---------------------------------------------------------------------------
__global__ __launch_bounds__(256) void vmix_kernel(
    const float* __restrict__ xt, const float* __restrict__ vf)
{
    __shared__ float f[256];
    f[threadIdx.x] = vf[threadIdx.x];
    __syncthreads();

    int idx = blockIdx.x * 256 + threadIdx.x;   // over B*T*64 = 262144
    int d = idx & 63;
    int t = (idx >> 6) & 2047;
    int b = idx >> 17;
    const float* xrow = xt + ((size_t)(b * TT + t)) * DD + d;
    float xv[16];
    #pragma unroll
    for (int j = 0; j < 16; j++) xv[j] = xrow[j * 64];
    #pragma unroll
    for (int i = 0; i < 16; i++) {
        float acc = 0.f;
        #pragma unroll
        for (int j = 0; j < 16; j++) acc = fmaf(f[i * 16 + j], xv[j], acc);
        g_v[(((size_t)(b * HH + i)) * TT + t) * HD + d] = acc;
    }
}

// ---------------------------------------------------------------------------
// Kernel 3: flash attention with causal mask + ALiBi.
// Block = (b, h, q-tile of 64). 256 threads as 16x16; 4x4 micro-tiles.
// smem: Qs [d][i] s68, Ks [d][j] s68 (reused as Ps [j][i]), Vs [j][d] s68.
// exp2-domain softmax; heavy tiles first; mask only on diagonal tile.
// K/V for tile kt+1 are prefetched into registers during tile kt's compute;
// P is staged to smem via in-register transpose + STS.128.
// ---------------------------------------------------------------------------
#define ASTRIDE 68
#define ATT_SMEM (3 * 64 * ASTRIDE * 4)
#define LOG2E 1.4426950408889634f

__global__ __launch_bounds__(256) void attn_kernel()
{
    extern __shared__ float sm[];
    float* Qs = sm;                       // [64][68] as [d][i]
    float* Ks = sm + 64 * ASTRIDE;        // [64][68] as [d][j]; reused as Ps[j][i]
    float* Vs = sm + 2 * 64 * ASTRIDE;    // [64][68] as [j][d]

    const int tid = threadIdx.x;
    const int tx = tid & 15;
    const int ty = tid >> 4;
    const int qt = (int)gridDim.x - 1 - (int)blockIdx.x;  // heavy tiles first
    const int h  = blockIdx.y;            // 0..15
    const int b  = blockIdx.z;            // 0..1
    const int q0 = qt * 64;

    const float scale2 = 0.125f * LOG2E;
    const float slope2 = exp2f(-0.5f * (float)(h + 1)) * LOG2E;

    const float* Qg = g_q + ((size_t)(b * HH + h) * TT) * HD;
    const float* Kg = g_k + ((size_t)(b * HH + h) * TT) * HD;
    const float* Vg = g_v + ((size_t)(b * HH + h) * TT) * HD;

    // Per-thread load slots: it-th slot covers row j=(tid+256it)>>4, cols d4..d4+3
    const int lj  = tid >> 4;              // 0..15, +16 per it
    const int ld4 = (tid & 15) << 2;       // 0,4,...,60

    // Load Q tile transposed: Qs[d][i] = Q[q0+i][d]
    #pragma unroll
    for (int it = 0; it < 4; it++) {
        int i = lj + it * 16;
        float4 v = *(const float4*)&Qg[(size_t)(q0 + i) * HD + ld4];
        Qs[(ld4 + 0) * ASTRIDE + i] = v.x;
        Qs[(ld4 + 1) * ASTRIDE + i] = v.y;
        Qs[(ld4 + 2) * ASTRIDE + i] = v.z;
        Qs[(ld4 + 3) * ASTRIDE + i] = v.w;
    }

    // Prefetch tile 0 into registers
    float4 pk[4], pv[4];
    #pragma unroll
    for (int it = 0; it < 4; it++) {
        int j = lj + it * 16;
        pk[it] = *(const float4*)&Kg[(size_t)j * HD + ld4];
        pv[it] = *(const float4*)&Vg[(size_t)j * HD + ld4];
    }

    float Ov[4][4];
    float mrow[4], lrow[4];
    #pragma unroll
    for (int i = 0; i < 4; i++) {
        mrow[i] = -1e30f; lrow[i] = 0.f;
        #pragma unroll
        for (int j = 0; j < 4; j++) Ov[i][j] = 0.f;
    }

    for (int kt = 0; kt <= qt; kt++) {
        // Publish prefetched K (transposed) and V (natural) to smem
        #pragma unroll
        for (int it = 0; it < 4; it++) {
            int j = lj + it * 16;
            Ks[(ld4 + 0) * ASTRIDE + j] = pk[it].x;
            Ks[(ld4 + 1) * ASTRIDE + j] = pk[it].y;
            Ks[(ld4 + 2) * ASTRIDE + j] = pk[it].z;
            Ks[(ld4 + 3) * ASTRIDE + j] = pk[it].w;
            *(float4*)&Vs[j * ASTRIDE + ld4] = pv[it];
        }
        __syncthreads();

        // Prefetch next tile while this tile computes
        if (kt < qt) {
            const int jn = (kt + 1) * 64;
            #pragma unroll
            for (int it = 0; it < 4; it++) {
                int j = jn + lj + it * 16;
                pk[it] = *(const float4*)&Kg[(size_t)j * HD + ld4];
                pv[it] = *(const float4*)&Vg[(size_t)j * HD + ld4];
            }
        }

        // S = Q K^T (4x4 per thread)
        const int j0 = kt * 64;
        float s[4][4];
        #pragma unroll
        for (int i = 0; i < 4; i++)
            #pragma unroll
            for (int j = 0; j < 4; j++) s[i][j] = 0.f;

        #pragma unroll 8
        for (int d = 0; d < 64; d++) {
            float4 aq = *(const float4*)&Qs[d * ASTRIDE + (ty << 2)];
            float4 bk = *(const float4*)&Ks[d * ASTRIDE + (tx << 2)];
            float av[4] = {aq.x, aq.y, aq.z, aq.w};
            float bv[4] = {bk.x, bk.y, bk.z, bk.w};
            #pragma unroll
            for (int ii = 0; ii < 4; ii++)
                #pragma unroll
                for (int jj = 0; jj < 4; jj++)
                    s[ii][jj] = fmaf(av[ii], bv[jj], s[ii][jj]);
        }

        // scale + ALiBi (exp2 domain); causal mask only on the diagonal tile
        if (kt < qt) {
            #pragma unroll
            for (int ii = 0; ii < 4; ii++) {
                int ig = q0 + (ty << 2) + ii;
                #pragma unroll
                for (int jj = 0; jj < 4; jj++) {
                    int jg = j0 + (tx << 2) + jj;
                    s[ii][jj] = fmaf(s[ii][jj], scale2, slope2 * (float)(jg - ig));
                }
            }
        } else {
            #pragma unroll
            for (int ii = 0; ii < 4; ii++) {
                int ig = q0 + (ty << 2) + ii;
                #pragma unroll
                for (int jj = 0; jj < 4; jj++) {
                    int jg = j0 + (tx << 2) + jj;
                    if (jg <= ig)
                        s[ii][jj] = fmaf(s[ii][jj], scale2, slope2 * (float)(jg - ig));
                    else
                        s[ii][jj] = -1e30f;
                }
            }
        }

        // online softmax update in exp2 domain (row stats across 16 tx lanes)
        #pragma unroll
        for (int ii = 0; ii < 4; ii++) {
            float tm = fmaxf(fmaxf(s[ii][0], s[ii][1]), fmaxf(s[ii][2], s[ii][3]));
            #pragma unroll
            for (int off = 1; off < 16; off <<= 1)
                tm = fmaxf(tm, __shfl_xor_sync(0xffffffffu, tm, off));
            float mn = fmaxf(mrow[ii], tm);
            float alpha = exp2f(mrow[ii] - mn);
            float ps = 0.f;
            #pragma unroll
            for (int jj = 0; jj < 4; jj++) {
                float p = exp2f(s[ii][jj] - mn);
                s[ii][jj] = p;
                ps += p;
            }
            #pragma unroll
            for (int off = 1; off < 16; off <<= 1)
                ps += __shfl_xor_sync(0xffffffffu, ps, off);
            lrow[ii] = lrow[ii] * alpha + ps;
            mrow[ii] = mn;
            #pragma unroll
            for (int dc = 0; dc < 4; dc++) Ov[ii][dc] *= alpha;
        }
        __syncthreads();   // everyone done reading Ks before overwrite with P

        // Ps[j][i] = P: in-register transpose -> STS.128
        // thread owns s[ii][jj] = P[q-row ty*4+ii][j0 + tx*4+jj]
        #pragma unroll
        for (int jj = 0; jj < 4; jj++) {
            float4 pc;
            pc.x = s[0][jj]; pc.y = s[1][jj]; pc.z = s[2][jj]; pc.w = s[3][jj];
            *(float4*)&Ks[((tx << 2) + jj) * ASTRIDE + (ty << 2)] = pc;
        }
        __syncthreads();

        // O += P @ V
        #pragma unroll 8
        for (int j = 0; j < 64; j++) {
            float4 ap = *(const float4*)&Ks[j * ASTRIDE + (ty << 2)];
            float4 vv = *(const float4*)&Vs[j * ASTRIDE + (tx << 2)];
            float av[4] = {ap.x, ap.y, ap.z, ap.w};
            float bv[4] = {vv.x, vv.y, vv.z, vv.w};
            #pragma unroll
            for (int ii = 0; ii < 4; ii++)
                #pragma unroll
                for (int dc = 0; dc < 4; dc++)
                    Ov[ii][dc] = fmaf(av[ii], bv[dc], Ov[ii][dc]);
        }
        __syncthreads();   // before next tile's stores overwrite Ks/Vs
    }

    // Normalize and write y[b,h,t,d]
    float* Yg = g_y + ((size_t)(b * HH + h) * TT) * HD;
    #pragma unroll
    for (int ii = 0; ii < 4; ii++) {
        float inv = 1.0f / lrow[ii];
        float4 o;
        o.x = Ov[ii][0] * inv;
        o.y = Ov[ii][1] * inv;
        o.z = Ov[ii][2] * inv;
        o.w = Ov[ii][3] * inv;
        *(float4*)&Yg[(size_t)(q0 + (ty << 2) + ii) * HD + (tx << 2)] = o;
    }
}

// ---------------------------------------------------------------------------
// Kernel 4: out[b,t,i*64+d] = sum_j out_fact[i,j] * y[b,j,t,d]
// ---------------------------------------------------------------------------
__global__ __launch_bounds__(256) void outmix_kernel(
    const float* __restrict__ of, float* __restrict__ out)
{
    __shared__ float f[256];
    f[threadIdx.x] = of[threadIdx.x];
    __syncthreads();

    int idx = blockIdx.x * 256 + threadIdx.x;   // over B*T*64
    int d = idx & 63;
    int t = (idx >> 6) & 2047;
    int b = idx >> 17;
    float yv[16];
    #pragma unroll
    for (int j = 0; j < 16; j++)
        yv[j] = g_y[(((size_t)(b * HH + j)) * TT + t) * HD + d];
    #pragma unroll
    for (int i = 0; i < 16; i++) {
        float acc = 0.f;
        #pragma unroll
        for (int j = 0; j < 16; j++) acc = fmaf(f[i * 16 + j], yv[j], acc);
        out[((size_t)(b * TT + t)) * DD + i * 64 + d] = acc;
    }
}

// ---------------------------------------------------------------------------
extern "C" void kernel_launch(void* const* d_in, const int* in_sizes, int n_in,
                              void* d_out, int out_size)
{
    const float* x_norm   = (const float*)d_in[0];
    const float* xt       = (const float*)d_in[1];
    const float* qk_w     = (const float*)d_in[2];
    const float* qk_b     = (const float*)d_in[3];
    const float* v_fact   = (const float*)d_in[4];
    const float* out_fact = (const float*)d_in[5];
    float* out = (float*)d_out;

    cudaFuncSetAttribute(attn_kernel,
                         cudaFuncAttributeMaxDynamicSharedMemorySize, ATT_SMEM);

    qk_gemm_kernel<<<dim3(16, 32), 256>>>(x_norm, qk_w, qk_b);
    vmix_kernel<<<1024, 256>>>(xt, v_fact);
    attn_kernel<<<dim3(32, 16, 2), 256, ATT_SMEM>>>();
    outmix_kernel<<<1024, 256>>>(out_fact, out);
}

// round 15
// speedup vs baseline: 1.3582x; 1.3582x over previous
#include <cuda_runtime.h>
#include <cuda_bf16.h>
#include <cstdint>

// Problem constants (fixed by setup_inputs)
#define BB 2
#define TT 2048
#define DD 1024
#define HH 16
#define HD 64

// Scratch: q,k,v,y in [B,H,T,hd] layout
__device__ float g_q[BB*HH*TT*HD];
__device__ float g_k[BB*HH*TT*HD];
__device__ float g_v[BB*HH*TT*HD];
__device__ float g_y[BB*HH*TT*HD];

// bf16 hi/lo split operands for the tensor-core GEMM
__device__ __nv_bfloat16 g_xhi[4096*1024];
__device__ __nv_bfloat16 g_xlo[4096*1024];
__device__ __nv_bfloat16 g_whi[2048*1024];
__device__ __nv_bfloat16 g_wlo[2048*1024];

__device__ __forceinline__ uint32_t smem_to_u32(const void* p) {
    uint32_t a;
    asm("{ .reg .u64 t; cvta.to.shared.u64 t, %1; cvt.u32.u64 %0, t; }"
        : "=r"(a) : "l"(p));
    return a;
}

// ---------------------------------------------------------------------------
// Kernel 0: split fp32 -> (hi, lo) bf16
// ---------------------------------------------------------------------------
__global__ __launch_bounds__(256) void split_kernel(
    const float* __restrict__ src, __nv_bfloat16* __restrict__ hi,
    __nv_bfloat16* __restrict__ lo)
{
    int i = (blockIdx.x * 256 + threadIdx.x) * 4;
    float4 v = *(const float4*)&src[i];
    __nv_bfloat16 h0 = __float2bfloat16(v.x);
    __nv_bfloat16 h1 = __float2bfloat16(v.y);
    __nv_bfloat16 h2 = __float2bfloat16(v.z);
    __nv_bfloat16 h3 = __float2bfloat16(v.w);
    __nv_bfloat16 l0 = __float2bfloat16(v.x - __bfloat162float(h0));
    __nv_bfloat16 l1 = __float2bfloat16(v.y - __bfloat162float(h1));
    __nv_bfloat16 l2 = __float2bfloat16(v.z - __bfloat162float(h2));
    __nv_bfloat16 l3 = __float2bfloat16(v.w - __bfloat162float(h3));
    __nv_bfloat162 hp0 = {h0, h1}, hp1 = {h2, h3};
    __nv_bfloat162 lp0 = {l0, l1}, lp1 = {l2, l3};
    uint2 hw, lw;
    hw.x = *(uint32_t*)&hp0; hw.y = *(uint32_t*)&hp1;
    lw.x = *(uint32_t*)&lp0; lw.y = *(uint32_t*)&lp1;
    *(uint2*)&hi[i] = hw;
    *(uint2*)&lo[i] = lw;
}

// ---------------------------------------------------------------------------
// Kernel 1: mma.sync bf16 split-precision GEMM (sm_80+ path; compiles on
// plain sm_103 targets, unlike tcgen05 which needs the 'a' feature target).
// qk[m][n] = sum_k x[m][k]*w[n][k] computed as hi@hi + hi@lo + lo@hi
// over virtual K=3072 (3 segments of K=1024).
// Block 128x128, BK=32; 8 warps (2x4); per-warp 64x32 via m16n8k16 tiles.
// ---------------------------------------------------------------------------
#define GPITCH 40   // bf16 elements per smem row (80B: ldmatrix conflict-free)

__global__ __launch_bounds__(256) void mma_gemm_kernel(const float* __restrict__ bias)
{
    __shared__ __nv_bfloat16 As[128 * GPITCH];
    __shared__ __nv_bfloat16 Bs[128 * GPITCH];

    const int tid  = threadIdx.x;
    const int lane = tid & 31;
    const int wid  = tid >> 5;
    const int warp_m = wid >> 2;      // 0..1 -> 64 rows each
    const int warp_n = wid & 3;       // 0..3 -> 32 cols each

    const int n0 = blockIdx.x * 128;  // 0..1920
    const int m0 = blockIdx.y * 128;  // 0..3968

    const __nv_bfloat16* Asegs[3] = {g_xhi, g_xhi, g_xlo};
    const __nv_bfloat16* Bsegs[3] = {g_whi, g_wlo, g_whi};

    // Global->smem slots: idx = tid + it*256; row = idx>>2 (0..127), q = idx&3
    const int grow = tid >> 2;            // 0..63 (+64 for it=1)
    const int gq   = (tid & 3) * 8;       // bf16 offset within the 32-wide chunk

    // ldmatrix per-lane source offsets (element index)
    const int a_row  = warp_m * 64 + (lane & 15);
    const int a_koff = (lane >> 4) * 8;                         // 0 or 8
    const int b_row  = warp_n * 32 + ((lane >> 4) & 1) * 8 + (lane & 7);
    const int b_koff = ((lane >> 3) & 1) * 8;                   // 0,8,0,8 per 8 lanes

    const uint32_t sA = smem_to_u32(As);
    const uint32_t sB = smem_to_u32(Bs);

    float acc[4][4][4];
    #pragma unroll
    for (int mt = 0; mt < 4; mt++)
        #pragma unroll
        for (int nt = 0; nt < 4; nt++)
            #pragma unroll
            for (int r = 0; r < 4; r++) acc[mt][nt][r] = 0.f;

    // Prefetch chunk 0 into registers
    uint4 pa[2], pb[2];
    {
        const __nv_bfloat16* Ag = Asegs[0];
        const __nv_bfloat16* Bg = Bsegs[0];
        #pragma unroll
        for (int it = 0; it < 2; it++) {
            int row = grow + it * 64;
            pa[it] = *(const uint4*)&Ag[(size_t)(m0 + row) * 1024 + gq];
            pb[it] = *(const uint4*)&Bg[(size_t)(n0 + row) * 1024 + gq];
        }
    }

    for (int c = 0; c < 96; c++) {
        // Publish prefetched chunk to smem
        #pragma unroll
        for (int it = 0; it < 2; it++) {
            int row = grow + it * 64;
            *(uint4*)&As[row * GPITCH + gq] = pa[it];
            *(uint4*)&Bs[row * GPITCH + gq] = pb[it];
        }
        __syncthreads();

        // Prefetch next chunk
        if (c < 95) {
            int cn = c + 1;
            const __nv_bfloat16* Ag = Asegs[cn >> 5];
            const __nv_bfloat16* Bg = Bsegs[cn >> 5];
            int kt = (cn & 31) * 32;
            #pragma unroll
            for (int it = 0; it < 2; it++) {
                int row = grow + it * 64;
                pa[it] = *(const uint4*)&Ag[(size_t)(m0 + row) * 1024 + kt + gq];
                pb[it] = *(const uint4*)&Bg[(size_t)(n0 + row) * 1024 + kt + gq];
            }
        }

        // Compute: 2 k16 steps over the 32-wide chunk
        #pragma unroll
        for (int kk = 0; kk < 32; kk += 16) {
            uint32_t aF[4][4];
            #pragma unroll
            for (int mt = 0; mt < 4; mt++) {
                uint32_t addr = sA + (uint32_t)(((a_row + mt * 16) * GPITCH + kk + a_koff) * 2);
                asm volatile(
                    "ldmatrix.sync.aligned.m8n8.x4.shared.b16 {%0,%1,%2,%3}, [%4];"
                    : "=r"(aF[mt][0]), "=r"(aF[mt][1]), "=r"(aF[mt][2]), "=r"(aF[mt][3])
                    : "r"(addr));
            }
            uint32_t bF[4][2];
            #pragma unroll
            for (int nt2 = 0; nt2 < 2; nt2++) {
                uint32_t addr = sB + (uint32_t)(((b_row + nt2 * 16) * GPITCH + kk + b_koff) * 2);
                uint32_t r0, r1, r2, r3;
                asm volatile(
                    "ldmatrix.sync.aligned.m8n8.x4.shared.b16 {%0,%1,%2,%3}, [%4];"
                    : "=r"(r0), "=r"(r1), "=r"(r2), "=r"(r3)
                    : "r"(addr));
                bF[nt2 * 2 + 0][0] = r0; bF[nt2 * 2 + 0][1] = r1;
                bF[nt2 * 2 + 1][0] = r2; bF[nt2 * 2 + 1][1] = r3;
            }
            #pragma unroll
            for (int mt = 0; mt < 4; mt++)
                #pragma unroll
                for (int nt = 0; nt < 4; nt++) {
                    asm volatile(
                        "mma.sync.aligned.m16n8k16.row.col.f32.bf16.bf16.f32 "
                        "{%0,%1,%2,%3}, {%4,%5,%6,%7}, {%8,%9}, {%0,%1,%2,%3};"
                        : "+f"(acc[mt][nt][0]), "+f"(acc[mt][nt][1]),
                          "+f"(acc[mt][nt][2]), "+f"(acc[mt][nt][3])
                        : "r"(aF[mt][0]), "r"(aF[mt][1]), "r"(aF[mt][2]), "r"(aF[mt][3]),
                          "r"(bF[nt][0]), "r"(bF[nt][1]));
                }
        }
        __syncthreads();
    }

    // Epilogue: bias add + scatter to head-major g_q/g_k (float2 pairs)
    #pragma unroll
    for (int mt = 0; mt < 4; mt++) {
        #pragma unroll
        for (int nt = 0; nt < 4; nt++) {
            int n = n0 + warp_n * 32 + nt * 8 + (lane & 3) * 2;
            float bz0 = bias[n], bz1 = bias[n + 1];
            int nn = n & 1023;
            int h = nn >> 6;
            int d = nn & 63;
            float* base = (n < 1024) ? g_q : g_k;
            #pragma unroll
            for (int half = 0; half < 2; half++) {
                int m = m0 + warp_m * 64 + mt * 16 + (lane >> 2) + half * 8;
                int b = m >> 11;
                int t = m & 2047;
                float2 v;
                v.x = acc[mt][nt][half * 2 + 0] + bz0;
                v.y = acc[mt][nt][half * 2 + 1] + bz1;
                *(float2*)&base[(((size_t)(b * HH + h) * TT + t)) * HD + d] = v;
            }
        }
    }
}

// ---------------------------------------------------------------------------
// Kernel 2: v[b,i,t,d] = sum_j v_fact[i,j] * xt[b,t,j*64+d]
// ---------------------------------------------------------------------------
__global__ __launch_bounds__(256) void vmix_kernel(
    const float* __restrict__ xt, const float* __restrict__ vf)
{
    __shared__ float f[256];
    f[threadIdx.x] = vf[threadIdx.x];
    __syncthreads();

    int idx = blockIdx.x * 256 + threadIdx.x;   // over B*T*64 = 262144
    int d = idx & 63;
    int t = (idx >> 6) & 2047;
    int b = idx >> 17;
    const float* xrow = xt + ((size_t)(b * TT + t)) * DD + d;
    float xv[16];
    #pragma unroll
    for (int j = 0; j < 16; j++) xv[j] = xrow[j * 64];
    #pragma unroll
    for (int i = 0; i < 16; i++) {
        float acc = 0.f;
        #pragma unroll
        for (int j = 0; j < 16; j++) acc = fmaf(f[i * 16 + j], xv[j], acc);
        g_v[(((size_t)(b * HH + i)) * TT + t) * HD + d] = acc;
    }
}

// ---------------------------------------------------------------------------
// Kernel 3: flash attention with causal mask + ALiBi (R5-passing version)
// ---------------------------------------------------------------------------
#define ASTRIDE 68
#define ATT_SMEM (3 * 64 * ASTRIDE * 4)
#define LOG2E 1.4426950408889634f

__global__ __launch_bounds__(256) void attn_kernel()
{
    extern __shared__ float sm[];
    float* Qs = sm;                       // [64][68] as [d][i]
    float* Ks = sm + 64 * ASTRIDE;        // [64][68] as [d][j]; reused as Ps[j][i]
    float* Vs = sm + 2 * 64 * ASTRIDE;    // [64][68] as [j][d]

    const int tid = threadIdx.x;
    const int tx = tid & 15;
    const int ty = tid >> 4;
    const int qt = (int)gridDim.x - 1 - (int)blockIdx.x;  // heavy tiles first
    const int h  = blockIdx.y;
    const int b  = blockIdx.z;
    const int q0 = qt * 64;

    const float scale2 = 0.125f * LOG2E;
    const float slope2 = exp2f(-0.5f * (float)(h + 1)) * LOG2E;

    const float* Qg = g_q + ((size_t)(b * HH + h) * TT) * HD;
    const float* Kg = g_k + ((size_t)(b * HH + h) * TT) * HD;
    const float* Vg = g_v + ((size_t)(b * HH + h) * TT) * HD;

    const int lj  = tid >> 4;
    const int ld4 = (tid & 15) << 2;

    #pragma unroll
    for (int it = 0; it < 4; it++) {
        int i = lj + it * 16;
        float4 v = *(const float4*)&Qg[(size_t)(q0 + i) * HD + ld4];
        Qs[(ld4 + 0) * ASTRIDE + i] = v.x;
        Qs[(ld4 + 1) * ASTRIDE + i] = v.y;
        Qs[(ld4 + 2) * ASTRIDE + i] = v.z;
        Qs[(ld4 + 3) * ASTRIDE + i] = v.w;
    }

    float4 pk[4], pv[4];
    #pragma unroll
    for (int it = 0; it < 4; it++) {
        int j = lj + it * 16;
        pk[it] = *(const float4*)&Kg[(size_t)j * HD + ld4];
        pv[it] = *(const float4*)&Vg[(size_t)j * HD + ld4];
    }

    float Ov[4][4];
    float mrow[4], lrow[4];
    #pragma unroll
    for (int i = 0; i < 4; i++) {
        mrow[i] = -1e30f; lrow[i] = 0.f;
        #pragma unroll
        for (int j = 0; j < 4; j++) Ov[i][j] = 0.f;
    }

    for (int kt = 0; kt <= qt; kt++) {
        #pragma unroll
        for (int it = 0; it < 4; it++) {
            int j = lj + it * 16;
            Ks[(ld4 + 0) * ASTRIDE + j] = pk[it].x;
            Ks[(ld4 + 1) * ASTRIDE + j] = pk[it].y;
            Ks[(ld4 + 2) * ASTRIDE + j] = pk[it].z;
            Ks[(ld4 + 3) * ASTRIDE + j] = pk[it].w;
            *(float4*)&Vs[j * ASTRIDE + ld4] = pv[it];
        }
        __syncthreads();

        if (kt < qt) {
            const int jn = (kt + 1) * 64;
            #pragma unroll
            for (int it = 0; it < 4; it++) {
                int j = jn + lj + it * 16;
                pk[it] = *(const float4*)&Kg[(size_t)j * HD + ld4];
                pv[it] = *(const float4*)&Vg[(size_t)j * HD + ld4];
            }
        }

        const int j0 = kt * 64;
        float s[4][4];
        #pragma unroll
        for (int i = 0; i < 4; i++)
            #pragma unroll
            for (int j = 0; j < 4; j++) s[i][j] = 0.f;

        #pragma unroll 8
        for (int d = 0; d < 64; d++) {
            float4 aq = *(const float4*)&Qs[d * ASTRIDE + (ty << 2)];
            float4 bk = *(const float4*)&Ks[d * ASTRIDE + (tx << 2)];
            float av[4] = {aq.x, aq.y, aq.z, aq.w};
            float bv[4] = {bk.x, bk.y, bk.z, bk.w};
            #pragma unroll
            for (int ii = 0; ii < 4; ii++)
                #pragma unroll
                for (int jj = 0; jj < 4; jj++)
                    s[ii][jj] = fmaf(av[ii], bv[jj], s[ii][jj]);
        }

        if (kt < qt) {
            #pragma unroll
            for (int ii = 0; ii < 4; ii++) {
                int ig = q0 + (ty << 2) + ii;
                #pragma unroll
                for (int jj = 0; jj < 4; jj++) {
                    int jg = j0 + (tx << 2) + jj;
                    s[ii][jj] = fmaf(s[ii][jj], scale2, slope2 * (float)(jg - ig));
                }
            }
        } else {
            #pragma unroll
            for (int ii = 0; ii < 4; ii++) {
                int ig = q0 + (ty << 2) + ii;
                #pragma unroll
                for (int jj = 0; jj < 4; jj++) {
                    int jg = j0 + (tx << 2) + jj;
                    if (jg <= ig)
                        s[ii][jj] = fmaf(s[ii][jj], scale2, slope2 * (float)(jg - ig));
                    else
                        s[ii][jj] = -1e30f;
                }
            }
        }

        #pragma unroll
        for (int ii = 0; ii < 4; ii++) {
            float tm = fmaxf(fmaxf(s[ii][0], s[ii][1]), fmaxf(s[ii][2], s[ii][3]));
            #pragma unroll
            for (int off = 1; off < 16; off <<= 1)
                tm = fmaxf(tm, __shfl_xor_sync(0xffffffffu, tm, off));
            float mn = fmaxf(mrow[ii], tm);
            float alpha = exp2f(mrow[ii] - mn);
            float ps = 0.f;
            #pragma unroll
            for (int jj = 0; jj < 4; jj++) {
                float p = exp2f(s[ii][jj] - mn);
                s[ii][jj] = p;
                ps += p;
            }
            #pragma unroll
            for (int off = 1; off < 16; off <<= 1)
                ps += __shfl_xor_sync(0xffffffffu, ps, off);
            lrow[ii] = lrow[ii] * alpha + ps;
            mrow[ii] = mn;
            #pragma unroll
            for (int dc = 0; dc < 4; dc++) Ov[ii][dc] *= alpha;
        }
        __syncthreads();

        #pragma unroll
        for (int jj = 0; jj < 4; jj++) {
            float4 pc;
            pc.x = s[0][jj]; pc.y = s[1][jj]; pc.z = s[2][jj]; pc.w = s[3][jj];
            *(float4*)&Ks[((tx << 2) + jj) * ASTRIDE + (ty << 2)] = pc;
        }
        __syncthreads();

        #pragma unroll 8
        for (int j = 0; j < 64; j++) {
            float4 ap = *(const float4*)&Ks[j * ASTRIDE + (ty << 2)];
            float4 vv = *(const float4*)&Vs[j * ASTRIDE + (tx << 2)];
            float av[4] = {ap.x, ap.y, ap.z, ap.w};
            float bv[4] = {vv.x, vv.y, vv.z, vv.w};
            #pragma unroll
            for (int ii = 0; ii < 4; ii++)
                #pragma unroll
                for (int dc = 0; dc < 4; dc++)
                    Ov[ii][dc] = fmaf(av[ii], bv[dc], Ov[ii][dc]);
        }
        __syncthreads();
    }

    float* Yg = g_y + ((size_t)(b * HH + h) * TT) * HD;
    #pragma unroll
    for (int ii = 0; ii < 4; ii++) {
        float inv = 1.0f / lrow[ii];
        float4 o;
        o.x = Ov[ii][0] * inv;
        o.y = Ov[ii][1] * inv;
        o.z = Ov[ii][2] * inv;
        o.w = Ov[ii][3] * inv;
        *(float4*)&Yg[(size_t)(q0 + (ty << 2) + ii) * HD + (tx << 2)] = o;
    }
}

// ---------------------------------------------------------------------------
// Kernel 4: out[b,t,i*64+d] = sum_j out_fact[i,j] * y[b,j,t,d]
// ---------------------------------------------------------------------------
__global__ __launch_bounds__(256) void outmix_kernel(
    const float* __restrict__ of, float* __restrict__ out)
{
    __shared__ float f[256];
    f[threadIdx.x] = of[threadIdx.x];
    __syncthreads();

    int idx = blockIdx.x * 256 + threadIdx.x;   // over B*T*64
    int d = idx & 63;
    int t = (idx >> 6) & 2047;
    int b = idx >> 17;
    float yv[16];
    #pragma unroll
    for (int j = 0; j < 16; j++)
        yv[j] = g_y[(((size_t)(b * HH + j)) * TT + t) * HD + d];
    #pragma unroll
    for (int i = 0; i < 16; i++) {
        float acc = 0.f;
        #pragma unroll
        for (int j = 0; j < 16; j++) acc = fmaf(f[i * 16 + j], yv[j], acc);
        out[((size_t)(b * TT + t)) * DD + i * 64 + d] = acc;
    }
}

// ---------------------------------------------------------------------------
extern "C" void kernel_launch(void* const* d_in, const int* in_sizes, int n_in,
                              void* d_out, int out_size)
{
    const float* x_norm   = (const float*)d_in[0];
    const float* xt       = (const float*)d_in[1];
    const float* qk_w     = (const float*)d_in[2];
    const float* qk_b     = (const float*)d_in[3];
    const float* v_fact   = (const float*)d_in[4];
    const float* out_fact = (const float*)d_in[5];
    float* out = (float*)d_out;

    __nv_bfloat16 *xhi, *xlo, *whi, *wlo;
    cudaGetSymbolAddress((void**)&xhi, g_xhi);
    cudaGetSymbolAddress((void**)&xlo, g_xlo);
    cudaGetSymbolAddress((void**)&whi, g_whi);
    cudaGetSymbolAddress((void**)&wlo, g_wlo);

    cudaFuncSetAttribute(attn_kernel,
                         cudaFuncAttributeMaxDynamicSharedMemorySize, ATT_SMEM);

    split_kernel<<<4096, 256>>>(x_norm, xhi, xlo);
    split_kernel<<<2048, 256>>>(qk_w, whi, wlo);
    mma_gemm_kernel<<<dim3(16, 32), 256>>>(qk_b);
    vmix_kernel<<<1024, 256>>>(xt, v_fact);
    attn_kernel<<<dim3(32, 16, 2), 256, ATT_SMEM>>>();
    outmix_kernel<<<1024, 256>>>(out_fact, out);
}